// round 5
// baseline (speedup 1.0000x reference)
#include <cuda_runtime.h>

// ---------------------------------------------------------------------------
// LSTM_Model: T=512, B=4096, I=1, H=16, two LSTM layers, then MLP 16->64->32->1
// Reference output = MLP(h2[:, B-1, :]) -> only batch row B-1 matters.
// ---------------------------------------------------------------------------

#define T_STEPS 512
#define H 16
#define FULL_MASK 0xffffffffu

// Scratch (device globals: no allocation allowed in kernel_launch)
__device__ float g_xsel[T_STEPS];        // x[t, B-1, 0]
__device__ float g_h2[T_STEPS * H];      // layer-2 hidden states for all t

__device__ __forceinline__ float sigm(float x) {
    return __fdividef(1.0f, 1.0f + __expf(-x));
}
__device__ __forceinline__ float tanh_(float x) {
    float e = __expf(-2.0f * x);
    return __fdividef(1.0f - e, 1.0f + e);
}

// ---------------------------------------------------------------------------
// Kernel 1: gather the single relevant batch row of x into packed scratch
// ---------------------------------------------------------------------------
__global__ void gather_x_kernel(const float* __restrict__ x, int B) {
    int t = blockIdx.x * blockDim.x + threadIdx.x;
    if (t < T_STEPS) {
        g_xsel[t] = x[t * B + (B - 1)];
    }
}

// ---------------------------------------------------------------------------
// Kernel 2: two-layer LSTM for the single sequence. One warp.
// Lane j (0..15) owns hidden unit j; lanes 16..31 duplicate (jj = lane & 15)
// so all 32 lanes stay converged for __shfl_sync.
// ---------------------------------------------------------------------------
__global__ void __launch_bounds__(32, 1) lstm_kernel(
    const float* __restrict__ Wih0, const float* __restrict__ Whh0,
    const float* __restrict__ bih0, const float* __restrict__ bhh0,
    const float* __restrict__ Wih1, const float* __restrict__ Whh1,
    const float* __restrict__ bih1, const float* __restrict__ bhh1)
{
    __shared__ float xs[T_STEPS];
    __shared__ float h1s[T_STEPS * H];

    const int lane = threadIdx.x;
    const int jj = lane & 15;

    // Stage x into shared
    for (int i = lane; i < T_STEPS; i += 32) xs[i] = g_xsel[i];
    __syncwarp();

    // ---------------- Layer 0 ----------------
    {
        float w_i[H], w_f[H], w_g[H], w_o[H];
#pragma unroll
        for (int k = 0; k < H; k++) {
            w_i[k] = Whh0[(jj +  0) * H + k];
            w_f[k] = Whh0[(jj + 16) * H + k];
            w_g[k] = Whh0[(jj + 32) * H + k];
            w_o[k] = Whh0[(jj + 48) * H + k];
        }
        // I = 1, so Wih0 is effectively a 64-vector
        const float wi_i = Wih0[jj +  0];
        const float wi_f = Wih0[jj + 16];
        const float wi_g = Wih0[jj + 32];
        const float wi_o = Wih0[jj + 48];
        const float b_i = bih0[jj +  0] + bhh0[jj +  0];
        const float b_f = bih0[jj + 16] + bhh0[jj + 16];
        const float b_g = bih0[jj + 32] + bhh0[jj + 32];
        const float b_o = bih0[jj + 48] + bhh0[jj + 48];

        float h = 0.0f, c = 0.0f;
        for (int t = 0; t < T_STEPS; t++) {
            const float xt = xs[t];
            float ai = fmaf(wi_i, xt, b_i);
            float af = fmaf(wi_f, xt, b_f);
            float ag = fmaf(wi_g, xt, b_g);
            float ao = fmaf(wi_o, xt, b_o);
#pragma unroll
            for (int k = 0; k < H; k++) {
                const float hk = __shfl_sync(FULL_MASK, h, k);
                ai = fmaf(w_i[k], hk, ai);
                af = fmaf(w_f[k], hk, af);
                ag = fmaf(w_g[k], hk, ag);
                ao = fmaf(w_o[k], hk, ao);
            }
            const float I = sigm(ai);
            const float F = sigm(af);
            const float G = tanh_(ag);
            const float O = sigm(ao);
            c = fmaf(F, c, I * G);
            h = O * tanh_(c);
            h1s[t * H + jj] = h;   // lanes j and j+16 write identical value
        }
    }
    __syncwarp();

    // ---------------- Layer 1 ----------------
    {
        float v_i[H], v_f[H], v_g[H], v_o[H];   // Whh1 rows
        float u_i[H], u_f[H], u_g[H], u_o[H];   // Wih1 rows
#pragma unroll
        for (int k = 0; k < H; k++) {
            v_i[k] = Whh1[(jj +  0) * H + k];
            v_f[k] = Whh1[(jj + 16) * H + k];
            v_g[k] = Whh1[(jj + 32) * H + k];
            v_o[k] = Whh1[(jj + 48) * H + k];
            u_i[k] = Wih1[(jj +  0) * H + k];
            u_f[k] = Wih1[(jj + 16) * H + k];
            u_g[k] = Wih1[(jj + 32) * H + k];
            u_o[k] = Wih1[(jj + 48) * H + k];
        }
        const float b_i = bih1[jj +  0] + bhh1[jj +  0];
        const float b_f = bih1[jj + 16] + bhh1[jj + 16];
        const float b_g = bih1[jj + 32] + bhh1[jj + 32];
        const float b_o = bih1[jj + 48] + bhh1[jj + 48];

        float h = 0.0f, c = 0.0f;
        for (int t = 0; t < T_STEPS; t++) {
            float ai = b_i, af = b_f, ag = b_g, ao = b_o;
            // input contribution: h1[t] (from shared, broadcast reads)
#pragma unroll
            for (int k = 0; k < H; k++) {
                const float xk = h1s[t * H + k];
                ai = fmaf(u_i[k], xk, ai);
                af = fmaf(u_f[k], xk, af);
                ag = fmaf(u_g[k], xk, ag);
                ao = fmaf(u_o[k], xk, ao);
            }
            // recurrent contribution via shuffle broadcast
#pragma unroll
            for (int k = 0; k < H; k++) {
                const float hk = __shfl_sync(FULL_MASK, h, k);
                ai = fmaf(v_i[k], hk, ai);
                af = fmaf(v_f[k], hk, af);
                ag = fmaf(v_g[k], hk, ag);
                ao = fmaf(v_o[k], hk, ao);
            }
            const float I = sigm(ai);
            const float F = sigm(af);
            const float G = tanh_(ag);
            const float O = sigm(ao);
            c = fmaf(F, c, I * G);
            h = O * tanh_(c);
            g_h2[t * H + jj] = h;   // benign duplicate write from twin lane
        }
    }
}

// ---------------------------------------------------------------------------
// Kernel 3: per-timestep MLP head 16 -> 64 -> 32 -> 1 on the 512 rows of g_h2
// ---------------------------------------------------------------------------
__global__ void __launch_bounds__(32) mlp_kernel(
    const float* __restrict__ W1, const float* __restrict__ b1,
    const float* __restrict__ W2, const float* __restrict__ b2,
    const float* __restrict__ W3, const float* __restrict__ b3,
    float* __restrict__ out)
{
    const int r = blockIdx.x * blockDim.x + threadIdx.x;
    if (r >= T_STEPS) return;

    float hv[H];
#pragma unroll
    for (int k = 0; k < H; k++) hv[k] = g_h2[r * H + k];

    float z1[64];
    for (int g = 0; g < 64; g++) {
        float a = b1[g];
        const float4* w = reinterpret_cast<const float4*>(W1 + g * H);
#pragma unroll
        for (int k4 = 0; k4 < H / 4; k4++) {
            float4 wv = w[k4];
            a = fmaf(wv.x, hv[k4 * 4 + 0], a);
            a = fmaf(wv.y, hv[k4 * 4 + 1], a);
            a = fmaf(wv.z, hv[k4 * 4 + 2], a);
            a = fmaf(wv.w, hv[k4 * 4 + 3], a);
        }
        z1[g] = fmaxf(a, 0.0f);
    }

    float z2[32];
    for (int g = 0; g < 32; g++) {
        float a = b2[g];
        const float4* w = reinterpret_cast<const float4*>(W2 + g * 64);
#pragma unroll
        for (int k4 = 0; k4 < 64 / 4; k4++) {
            float4 wv = w[k4];
            a = fmaf(wv.x, z1[k4 * 4 + 0], a);
            a = fmaf(wv.y, z1[k4 * 4 + 1], a);
            a = fmaf(wv.z, z1[k4 * 4 + 2], a);
            a = fmaf(wv.w, z1[k4 * 4 + 3], a);
        }
        z2[g] = fmaxf(a, 0.0f);
    }

    float a = b3[0];
#pragma unroll
    for (int k = 0; k < 32; k++) a = fmaf(W3[k], z2[k], a);
    out[r] = a;
}

// ---------------------------------------------------------------------------
extern "C" void kernel_launch(void* const* d_in, const int* in_sizes, int n_in,
                              void* d_out, int out_size)
{
    const float* x    = (const float*)d_in[0];
    const float* Wih0 = (const float*)d_in[1];
    const float* Whh0 = (const float*)d_in[2];
    const float* bih0 = (const float*)d_in[3];
    const float* bhh0 = (const float*)d_in[4];
    const float* Wih1 = (const float*)d_in[5];
    const float* Whh1 = (const float*)d_in[6];
    const float* bih1 = (const float*)d_in[7];
    const float* bhh1 = (const float*)d_in[8];
    const float* W1   = (const float*)d_in[9];
    const float* b1   = (const float*)d_in[10];
    const float* W2   = (const float*)d_in[11];
    const float* b2   = (const float*)d_in[12];
    const float* W3   = (const float*)d_in[13];
    const float* b3   = (const float*)d_in[14];

    const int B = in_sizes[0] / T_STEPS;   // 4096 (I = 1)

    gather_x_kernel<<<2, 256>>>(x, B);
    lstm_kernel<<<1, 32>>>(Wih0, Whh0, bih0, bhh0, Wih1, Whh1, bih1, bhh1);
    mlp_kernel<<<16, 32>>>(W1, b1, W2, b2, W3, b3, (float*)d_out);
}

// round 6
// speedup vs baseline: 2.6130x; 2.6130x over previous
#include <cuda_runtime.h>

// ---------------------------------------------------------------------------
// LSTM_Model: T=512, B=4096, I=1, H=16, two LSTM layers, then MLP 16->64->32->1
// Reference output = MLP(h2[:, B-1, :]) -> only batch row B-1 matters.
//
// Fused 3-warp pipelined kernel:
//   warp 0: layer-0 recurrence (gate-split, 2 gates/lane)
//   warp 1: layer-1 input-gate precompute xg1[t] = Wih1 @ h1[t] + b  (lag 1 blk)
//   warp 2: layer-1 recurrence consuming xg1                          (lag 2 blk)
// __syncthreads() every BLK=8 steps provides sync + STS drain.
// ---------------------------------------------------------------------------

#define T_STEPS 512
#define H 16
#define BLK 8
#define NB (T_STEPS / BLK)
#define FULL_MASK 0xffffffffu

__device__ float g_h2[T_STEPS * H];   // layer-2 hidden states (global for MLP kernel)

__device__ __forceinline__ float tanh_(float x) {
    float e = __expf(-2.0f * x);
    return __fdividef(1.0f - e, 1.0f + e);
}

// One gate-split LSTM step.
// lane l<16  : unit j=l,    owns gates i (row l)    and g (row l+32)
// lane l>=16 : unit j=l-16, owns gates f (row l)    and o (row l+32)
// h, c are replicated on both halves (lane j and lane j+16 hold identical values).
__device__ __forceinline__ void lstm_step(
    float aA, float aB,                        // input parts incl. biases
    const float* __restrict__ wA,
    const float* __restrict__ wB,
    bool lower, float mulB,
    float& h, float& c)
{
    // recurrent dot: 2 partial accumulators per gate to shorten the chain
    float s0 = aA, s1 = 0.0f, s2 = aB, s3 = 0.0f;
#pragma unroll
    for (int k = 0; k < H; k += 2) {
        float hk0 = __shfl_sync(FULL_MASK, h, k);
        float hk1 = __shfl_sync(FULL_MASK, h, k + 1);
        s0 = fmaf(wA[k],     hk0, s0);
        s2 = fmaf(wB[k],     hk0, s2);
        s1 = fmaf(wA[k + 1], hk1, s1);
        s3 = fmaf(wB[k + 1], hk1, s3);
    }
    aA = s0 + s1;
    aB = s2 + s3;

    // gate A is sigmoid on both halves (i on lower, f on upper)
    float eA = __expf(-aA);
    float A  = __fdividef(1.0f, 1.0f + eA);
    // gate B: tanh(g) on lower (e = exp(-2x)), sigmoid(o) on upper (e = exp(-x))
    float eB = __expf(mulB * aB);
    float rB = __fdividef(1.0f, 1.0f + eB);
    float Bv = lower ? (1.0f - eB) * rB : rB;

    float P  = A * Bv;                          // lower: i*g (upper value unused)
    float send1 = lower ? P : A;                // lower sends i*g, upper sends f
    float r1 = __shfl_xor_sync(FULL_MASK, send1, 16);
    float F  = lower ? r1 : A;
    float Pu = lower ? P  : r1;
    c = fmaf(F, c, Pu);
    float tc = tanh_(c);
    float r2 = __shfl_xor_sync(FULL_MASK, Bv, 16); // lower receives o
    float O  = lower ? r2 : Bv;
    h = O * tc;
}

// ---------------------------------------------------------------------------
__global__ void __launch_bounds__(96, 1) lstm_fused_kernel(
    const float* __restrict__ x, int B,
    const float* __restrict__ Wih0, const float* __restrict__ Whh0,
    const float* __restrict__ bih0, const float* __restrict__ bhh0,
    const float* __restrict__ Wih1, const float* __restrict__ Whh1,
    const float* __restrict__ bih1, const float* __restrict__ bhh1)
{
    extern __shared__ float smem[];
    float* xs  = smem;                       // [512]
    float* h1s = smem + T_STEPS;             // [512 * 16]
    float* xg1 = h1s + T_STEPS * H;          // [512 * 64]

    const int tid  = threadIdx.x;
    const int wid  = tid >> 5;
    const int lane = tid & 31;
    const bool lower = (lane < 16);
    const float mulB = lower ? -2.0f : -1.0f;
    const int l = lane;

    // gather the single relevant batch row of x
    for (int t = tid; t < T_STEPS; t += 96)
        xs[t] = x[(size_t)t * B + (B - 1)];

    // per-role weights in registers
    float wA[H], wB[H];     // recurrence weights (warp 0: Whh0, warp 2: Whh1)
    float uA[H], uB[H];     // warp 1: Wih1 rows
    float bA = 0.0f, bB = 0.0f, wiA = 0.0f, wiB = 0.0f;

    if (wid == 0) {
#pragma unroll
        for (int k = 0; k < H; k++) {
            wA[k] = Whh0[l * H + k];
            wB[k] = Whh0[(l + 32) * H + k];
        }
        wiA = Wih0[l];       wiB = Wih0[l + 32];          // I = 1
        bA  = bih0[l] + bhh0[l];
        bB  = bih0[l + 32] + bhh0[l + 32];
    } else if (wid == 1) {
#pragma unroll
        for (int k = 0; k < H; k++) {
            uA[k] = Wih1[l * H + k];
            uB[k] = Wih1[(l + 32) * H + k];
        }
        bA = bih1[l] + bhh1[l];
        bB = bih1[l + 32] + bhh1[l + 32];
    } else if (wid == 2) {
#pragma unroll
        for (int k = 0; k < H; k++) {
            wA[k] = Whh1[l * H + k];
            wB[k] = Whh1[(l + 32) * H + k];
        }
    }
    __syncthreads();

    float h = 0.0f, c = 0.0f;

    for (int blk = 0; blk < NB + 2; blk++) {
        if (wid == 0) {
            if (blk < NB) {
                const int t0 = blk * BLK;
#pragma unroll 1
                for (int s = 0; s < BLK; s++) {
                    const int t = t0 + s;
                    const float xt = xs[t];
                    lstm_step(fmaf(wiA, xt, bA), fmaf(wiB, xt, bB),
                              wA, wB, lower, mulB, h, c);
                    if (lower) h1s[t * H + lane] = h;
                }
            }
        } else if (wid == 1) {
            if (blk >= 1 && blk <= NB) {
                const int t0 = (blk - 1) * BLK;
#pragma unroll 1
                for (int s = 0; s < BLK; s++) {
                    const int t = t0 + s;
                    const float4* hp = reinterpret_cast<const float4*>(h1s + t * H);
                    float a = bA, b = bB;
#pragma unroll
                    for (int q = 0; q < 4; q++) {
                        float4 h4 = hp[q];                   // broadcast LDS.128
                        a = fmaf(uA[q * 4 + 0], h4.x, a);
                        b = fmaf(uB[q * 4 + 0], h4.x, b);
                        a = fmaf(uA[q * 4 + 1], h4.y, a);
                        b = fmaf(uB[q * 4 + 1], h4.y, b);
                        a = fmaf(uA[q * 4 + 2], h4.z, a);
                        b = fmaf(uB[q * 4 + 2], h4.z, b);
                        a = fmaf(uA[q * 4 + 3], h4.w, a);
                        b = fmaf(uB[q * 4 + 3], h4.w, b);
                    }
                    xg1[t * 64 + l]      = a;   // conflict-free (consecutive lanes)
                    xg1[t * 64 + l + 32] = b;
                }
            }
        } else if (wid == 2) {
            if (blk >= 2) {
                const int t0 = (blk - 2) * BLK;
#pragma unroll 1
                for (int s = 0; s < BLK; s++) {
                    const int t = t0 + s;
                    lstm_step(xg1[t * 64 + l], xg1[t * 64 + l + 32],
                              wA, wB, lower, mulB, h, c);
                    if (lower) g_h2[t * H + lane] = h;
                }
            }
        }
        __syncthreads();   // uniform: all 96 threads, every round; drains STS
    }
}

// ---------------------------------------------------------------------------
// MLP head 16 -> 64 -> 32 -> 1 on the 512 rows of g_h2 (wide, separate kernel)
// ---------------------------------------------------------------------------
__global__ void __launch_bounds__(32) mlp_kernel(
    const float* __restrict__ W1, const float* __restrict__ b1,
    const float* __restrict__ W2, const float* __restrict__ b2,
    const float* __restrict__ W3, const float* __restrict__ b3,
    float* __restrict__ out)
{
    const int r = blockIdx.x * blockDim.x + threadIdx.x;
    if (r >= T_STEPS) return;

    float hv[H];
#pragma unroll
    for (int k = 0; k < H; k++) hv[k] = g_h2[r * H + k];

    float z1[64];
    for (int g = 0; g < 64; g++) {
        float a = b1[g];
        const float4* w = reinterpret_cast<const float4*>(W1 + g * H);
#pragma unroll
        for (int k4 = 0; k4 < H / 4; k4++) {
            float4 wv = w[k4];
            a = fmaf(wv.x, hv[k4 * 4 + 0], a);
            a = fmaf(wv.y, hv[k4 * 4 + 1], a);
            a = fmaf(wv.z, hv[k4 * 4 + 2], a);
            a = fmaf(wv.w, hv[k4 * 4 + 3], a);
        }
        z1[g] = fmaxf(a, 0.0f);
    }

    float z2[32];
    for (int g = 0; g < 32; g++) {
        float a = b2[g];
        const float4* w = reinterpret_cast<const float4*>(W2 + g * 64);
#pragma unroll
        for (int k4 = 0; k4 < 64 / 4; k4++) {
            float4 wv = w[k4];
            a = fmaf(wv.x, z1[k4 * 4 + 0], a);
            a = fmaf(wv.y, z1[k4 * 4 + 1], a);
            a = fmaf(wv.z, z1[k4 * 4 + 2], a);
            a = fmaf(wv.w, z1[k4 * 4 + 3], a);
        }
        z2[g] = fmaxf(a, 0.0f);
    }

    float a = b3[0];
#pragma unroll
    for (int k = 0; k < 32; k++) a = fmaf(W3[k], z2[k], a);
    out[r] = a;
}

// ---------------------------------------------------------------------------
extern "C" void kernel_launch(void* const* d_in, const int* in_sizes, int n_in,
                              void* d_out, int out_size)
{
    const float* x    = (const float*)d_in[0];
    const float* Wih0 = (const float*)d_in[1];
    const float* Whh0 = (const float*)d_in[2];
    const float* bih0 = (const float*)d_in[3];
    const float* bhh0 = (const float*)d_in[4];
    const float* Wih1 = (const float*)d_in[5];
    const float* Whh1 = (const float*)d_in[6];
    const float* bih1 = (const float*)d_in[7];
    const float* bhh1 = (const float*)d_in[8];
    const float* W1   = (const float*)d_in[9];
    const float* b1   = (const float*)d_in[10];
    const float* W2   = (const float*)d_in[11];
    const float* b2   = (const float*)d_in[12];
    const float* W3   = (const float*)d_in[13];
    const float* b3   = (const float*)d_in[14];

    const int B = in_sizes[0] / T_STEPS;   // 4096 (I = 1)

    // dynamic smem: xs(512) + h1s(512*16) + xg1(512*64) floats = 165,888 bytes
    const int smem_bytes = (T_STEPS + T_STEPS * H + T_STEPS * 64) * (int)sizeof(float);
    static bool attr_set = false;
    if (!attr_set) {
        cudaFuncSetAttribute(lstm_fused_kernel,
                             cudaFuncAttributeMaxDynamicSharedMemorySize, smem_bytes);
        attr_set = true;
    }

    lstm_fused_kernel<<<1, 96, smem_bytes>>>(x, B,
        Wih0, Whh0, bih0, bhh0, Wih1, Whh1, bih1, bhh1);
    mlp_kernel<<<16, 32>>>(W1, b1, W2, b2, W3, b3, (float*)d_out);
}

// round 7
// speedup vs baseline: 3.8035x; 1.4556x over previous
#include <cuda_runtime.h>

// ---------------------------------------------------------------------------
// LSTM_Model: T=512, B=4096, I=1, H=16, two LSTM layers, then MLP 16->64->32->1
// Reference output = MLP(h2[:, B-1, :]) -> only batch row B-1 matters.
//
// Fused 3-warp pipelined kernel:
//   warp 0: layer-0 recurrence (gate-split, 2 gates/lane)
//   warp 1: layer-1 input-gate precompute xg1[t] = Wih1 @ h1[t] + b  (lag 1 blk)
//   warp 2: layer-1 recurrence consuming xg1                          (lag 2 blk)
// Activations use tanh.approx.f32 (single MUFU op) to shorten the serial chain.
// ---------------------------------------------------------------------------

#define T_STEPS 512
#define H 16
#define BLK 8
#define NB (T_STEPS / BLK)
#define FULL_MASK 0xffffffffu

__device__ float g_h2[T_STEPS * H];   // layer-2 hidden states (global for MLP kernel)

__device__ __forceinline__ float tanh_fast(float x) {
    float y;
    asm("tanh.approx.f32 %0, %1;" : "=f"(y) : "f"(x));
    return y;
}

// One gate-split LSTM step.
// lane l<16  : unit j=l,    owns gates i (row l)    and g (row l+32)
// lane l>=16 : unit j=l-16, owns gates f (row l)    and o (row l+32)
// h, c are replicated on both halves (lane j and lane j+16 hold identical values).
__device__ __forceinline__ void lstm_step(
    float aA, float aB,                        // input parts incl. biases
    const float* __restrict__ wA,
    const float* __restrict__ wB,
    bool lower,
    float& h, float& c)
{
    // recurrent dot: 4 partial accumulators per gate (chain depth 4 + add tree)
    float s0 = aA,  s1 = 0.0f, s2 = 0.0f, s3 = 0.0f;
    float q0 = aB,  q1 = 0.0f, q2 = 0.0f, q3 = 0.0f;
#pragma unroll
    for (int k = 0; k < H; k += 4) {
        float h0 = __shfl_sync(FULL_MASK, h, k);
        float h1 = __shfl_sync(FULL_MASK, h, k + 1);
        float h2 = __shfl_sync(FULL_MASK, h, k + 2);
        float h3 = __shfl_sync(FULL_MASK, h, k + 3);
        s0 = fmaf(wA[k],     h0, s0);  q0 = fmaf(wB[k],     h0, q0);
        s1 = fmaf(wA[k + 1], h1, s1);  q1 = fmaf(wB[k + 1], h1, q1);
        s2 = fmaf(wA[k + 2], h2, s2);  q2 = fmaf(wB[k + 2], h2, q2);
        s3 = fmaf(wA[k + 3], h3, s3);  q3 = fmaf(wB[k + 3], h3, q3);
    }
    aA = (s0 + s1) + (s2 + s3);
    aB = (q0 + q1) + (q2 + q3);

    // gate A is sigmoid on both halves (i on lower, f on upper):
    //   sigma(x) = 0.5*tanh(0.5x) + 0.5
    float A = fmaf(0.5f, tanh_fast(0.5f * aA), 0.5f);
    // gate B: tanh(g) on lower, sigmoid(o) on upper
    float tB = tanh_fast(lower ? aB : 0.5f * aB);
    float Bv = lower ? tB : fmaf(0.5f, tB, 0.5f);

    float P  = A * Bv;                          // lower: i*g (upper value unused)
    float send1 = lower ? P : A;                // lower sends i*g, upper sends f
    float r1 = __shfl_xor_sync(FULL_MASK, send1, 16);
    float F  = lower ? r1 : A;
    float Pu = lower ? P  : r1;
    c = fmaf(F, c, Pu);
    float tc = tanh_fast(c);
    float r2 = __shfl_xor_sync(FULL_MASK, Bv, 16); // lower receives o
    float O  = lower ? r2 : Bv;
    h = O * tc;
}

// ---------------------------------------------------------------------------
__global__ void __launch_bounds__(96, 1) lstm_fused_kernel(
    const float* __restrict__ x, int B,
    const float* __restrict__ Wih0, const float* __restrict__ Whh0,
    const float* __restrict__ bih0, const float* __restrict__ bhh0,
    const float* __restrict__ Wih1, const float* __restrict__ Whh1,
    const float* __restrict__ bih1, const float* __restrict__ bhh1)
{
    extern __shared__ float smem[];
    float* xs  = smem;                       // [512]
    float* h1s = smem + T_STEPS;             // [512 * 16]
    float* xg1 = h1s + T_STEPS * H;          // [512 * 64]

    const int tid  = threadIdx.x;
    const int wid  = tid >> 5;
    const int lane = tid & 31;
    const bool lower = (lane < 16);
    const int l = lane;

    // gather the single relevant batch row of x
    for (int t = tid; t < T_STEPS; t += 96)
        xs[t] = x[(size_t)t * B + (B - 1)];

    // per-role weights in registers
    float wA[H], wB[H];     // recurrence weights (warp 0: Whh0, warp 2: Whh1)
    float uA[H], uB[H];     // warp 1: Wih1 rows
    float bA = 0.0f, bB = 0.0f, wiA = 0.0f, wiB = 0.0f;

    if (wid == 0) {
#pragma unroll
        for (int k = 0; k < H; k++) {
            wA[k] = Whh0[l * H + k];
            wB[k] = Whh0[(l + 32) * H + k];
        }
        wiA = Wih0[l];       wiB = Wih0[l + 32];          // I = 1
        bA  = bih0[l] + bhh0[l];
        bB  = bih0[l + 32] + bhh0[l + 32];
    } else if (wid == 1) {
#pragma unroll
        for (int k = 0; k < H; k++) {
            uA[k] = Wih1[l * H + k];
            uB[k] = Wih1[(l + 32) * H + k];
        }
        bA = bih1[l] + bhh1[l];
        bB = bih1[l + 32] + bhh1[l + 32];
    } else if (wid == 2) {
#pragma unroll
        for (int k = 0; k < H; k++) {
            wA[k] = Whh1[l * H + k];
            wB[k] = Whh1[(l + 32) * H + k];
        }
    }
    __syncthreads();

    float h = 0.0f, c = 0.0f;

    for (int blk = 0; blk < NB + 2; blk++) {
        if (wid == 0) {
            if (blk < NB) {
                const int t0 = blk * BLK;
#pragma unroll 1
                for (int s = 0; s < BLK; s++) {
                    const int t = t0 + s;
                    const float xt = xs[t];
                    lstm_step(fmaf(wiA, xt, bA), fmaf(wiB, xt, bB),
                              wA, wB, lower, h, c);
                    if (lower) h1s[t * H + lane] = h;
                }
            }
        } else if (wid == 1) {
            if (blk >= 1 && blk <= NB) {
                const int t0 = (blk - 1) * BLK;
#pragma unroll 1
                for (int s = 0; s < BLK; s++) {
                    const int t = t0 + s;
                    const float4* hp = reinterpret_cast<const float4*>(h1s + t * H);
                    float a = bA, b = bB;
#pragma unroll
                    for (int q = 0; q < 4; q++) {
                        float4 h4 = hp[q];                   // broadcast LDS.128
                        a = fmaf(uA[q * 4 + 0], h4.x, a);
                        b = fmaf(uB[q * 4 + 0], h4.x, b);
                        a = fmaf(uA[q * 4 + 1], h4.y, a);
                        b = fmaf(uB[q * 4 + 1], h4.y, b);
                        a = fmaf(uA[q * 4 + 2], h4.z, a);
                        b = fmaf(uB[q * 4 + 2], h4.z, b);
                        a = fmaf(uA[q * 4 + 3], h4.w, a);
                        b = fmaf(uB[q * 4 + 3], h4.w, b);
                    }
                    xg1[t * 64 + l]      = a;   // conflict-free (consecutive lanes)
                    xg1[t * 64 + l + 32] = b;
                }
            }
        } else if (wid == 2) {
            if (blk >= 2) {
                const int t0 = (blk - 2) * BLK;
#pragma unroll 1
                for (int s = 0; s < BLK; s++) {
                    const int t = t0 + s;
                    lstm_step(xg1[t * 64 + l], xg1[t * 64 + l + 32],
                              wA, wB, lower, h, c);
                    if (lower) g_h2[t * H + lane] = h;
                }
            }
        }
        __syncthreads();   // uniform: all 96 threads, every round; drains STS
    }
}

// ---------------------------------------------------------------------------
// MLP head 16 -> 64 -> 32 -> 1 on the 512 rows of g_h2.
// Weights staged into shared per block (12.8 KB) -> LDS broadcast, no L2 stalls.
// ---------------------------------------------------------------------------
__global__ void __launch_bounds__(32) mlp_kernel(
    const float* __restrict__ W1, const float* __restrict__ b1,
    const float* __restrict__ W2, const float* __restrict__ b2,
    const float* __restrict__ W3, const float* __restrict__ b3,
    float* __restrict__ out)
{
    __shared__ float sW1[64 * H];    // 1024
    __shared__ float sW2[32 * 64];   // 2048
    __shared__ float sb1[64];
    __shared__ float sb2[32];
    __shared__ float sW3[32];

    const int tid = threadIdx.x;

    // stage weights (vectorized, coalesced)
    for (int i = tid; i < (64 * H) / 4; i += 32)
        reinterpret_cast<float4*>(sW1)[i] = reinterpret_cast<const float4*>(W1)[i];
    for (int i = tid; i < (32 * 64) / 4; i += 32)
        reinterpret_cast<float4*>(sW2)[i] = reinterpret_cast<const float4*>(W2)[i];
    if (tid < 16) reinterpret_cast<float4*>(sb1)[tid] = reinterpret_cast<const float4*>(b1)[tid];
    if (tid < 8)  reinterpret_cast<float4*>(sb2)[tid] = reinterpret_cast<const float4*>(b2)[tid];
    if (tid < 8)  reinterpret_cast<float4*>(sW3)[tid] = reinterpret_cast<const float4*>(W3)[tid];
    __syncthreads();

    const int r = blockIdx.x * 32 + tid;   // 16 blocks * 32 = 512 rows
    const float bias3 = b3[0];

    float hv[H];
    const float4* hp = reinterpret_cast<const float4*>(g_h2 + r * H);
#pragma unroll
    for (int q = 0; q < H / 4; q++) {
        float4 v = hp[q];
        hv[q * 4 + 0] = v.x; hv[q * 4 + 1] = v.y;
        hv[q * 4 + 2] = v.z; hv[q * 4 + 3] = v.w;
    }

    float z1[64];
#pragma unroll 4
    for (int g = 0; g < 64; g++) {
        float a = sb1[g];
        const float4* w = reinterpret_cast<const float4*>(sW1 + g * H);
#pragma unroll
        for (int k4 = 0; k4 < H / 4; k4++) {
            float4 wv = w[k4];
            a = fmaf(wv.x, hv[k4 * 4 + 0], a);
            a = fmaf(wv.y, hv[k4 * 4 + 1], a);
            a = fmaf(wv.z, hv[k4 * 4 + 2], a);
            a = fmaf(wv.w, hv[k4 * 4 + 3], a);
        }
        z1[g] = fmaxf(a, 0.0f);
    }

    float z2[32];
#pragma unroll 2
    for (int g = 0; g < 32; g++) {
        float a = sb2[g];
        const float4* w = reinterpret_cast<const float4*>(sW2 + g * 64);
#pragma unroll
        for (int k4 = 0; k4 < 64 / 4; k4++) {
            float4 wv = w[k4];
            a = fmaf(wv.x, z1[k4 * 4 + 0], a);
            a = fmaf(wv.y, z1[k4 * 4 + 1], a);
            a = fmaf(wv.z, z1[k4 * 4 + 2], a);
            a = fmaf(wv.w, z1[k4 * 4 + 3], a);
        }
        z2[g] = fmaxf(a, 0.0f);
    }

    float a = bias3;
#pragma unroll
    for (int k = 0; k < 32; k++) a = fmaf(sW3[k], z2[k], a);
    out[r] = a;
}

// ---------------------------------------------------------------------------
extern "C" void kernel_launch(void* const* d_in, const int* in_sizes, int n_in,
                              void* d_out, int out_size)
{
    const float* x    = (const float*)d_in[0];
    const float* Wih0 = (const float*)d_in[1];
    const float* Whh0 = (const float*)d_in[2];
    const float* bih0 = (const float*)d_in[3];
    const float* bhh0 = (const float*)d_in[4];
    const float* Wih1 = (const float*)d_in[5];
    const float* Whh1 = (const float*)d_in[6];
    const float* bih1 = (const float*)d_in[7];
    const float* bhh1 = (const float*)d_in[8];
    const float* W1   = (const float*)d_in[9];
    const float* b1   = (const float*)d_in[10];
    const float* W2   = (const float*)d_in[11];
    const float* b2   = (const float*)d_in[12];
    const float* W3   = (const float*)d_in[13];
    const float* b3   = (const float*)d_in[14];

    const int B = in_sizes[0] / T_STEPS;   // 4096 (I = 1)

    // dynamic smem: xs(512) + h1s(512*16) + xg1(512*64) floats = 165,888 bytes
    const int smem_bytes = (T_STEPS + T_STEPS * H + T_STEPS * 64) * (int)sizeof(float);
    cudaFuncSetAttribute(lstm_fused_kernel,
                         cudaFuncAttributeMaxDynamicSharedMemorySize, smem_bytes);

    lstm_fused_kernel<<<1, 96, smem_bytes>>>(x, B,
        Wih0, Whh0, bih0, bhh0, Wih1, Whh1, bih1, bhh1);
    mlp_kernel<<<16, 32>>>(W1, b1, W2, b2, W3, b3, (float*)d_out);
}

// round 8
// speedup vs baseline: 3.8785x; 1.0197x over previous
#include <cuda_runtime.h>

// ---------------------------------------------------------------------------
// LSTM_Model: T=512, B=4096, I=1, H=16, two LSTM layers, then MLP 16->64->32->1
// Reference output = MLP(h2[:, B-1, :]) -> only batch row B-1 matters.
//
// Fused 3-warp pipelined kernel:
//   warp 0: layer-0 recurrence (gate-split, 2 gates/lane)
//   warp 1: layer-1 input-gate precompute xg1[t] = Wih1 @ h1[t] + b  (lag 1 blk)
//   warp 2: layer-1 recurrence consuming xg1                          (lag 2 blk)
// Activations via tanh.approx.f32; per-lane activation constants (no SELs).
// ---------------------------------------------------------------------------

#define T_STEPS 512
#define H 16
#define BLK 16
#define NB (T_STEPS / BLK)
#define FULL_MASK 0xffffffffu

__device__ float g_h2[T_STEPS * H];   // layer-2 hidden states (global for MLP kernel)

__device__ __forceinline__ float tanh_fast(float x) {
    float y;
    asm("tanh.approx.f32 %0, %1;" : "=f"(y) : "f"(x));
    return y;
}

// One gate-split LSTM step.
// lane l<16  : unit j=l,    owns gates i (row l)    and g (row l+32)
// lane l>=16 : unit j=l-16, owns gates f (row l)    and o (row l+32)
// h, c replicated on both halves.
// mB/cB/dB: lower -> (1, 1, 0)  [Bv = tanh(aB)]
//           upper -> (0.5, 0.5, 0.5) [Bv = sigmoid(aB)]
__device__ __forceinline__ void lstm_step(
    float aA, float aB,
    const float* __restrict__ wA,
    const float* __restrict__ wB,
    bool lower, float mB, float cB, float dB,
    float& h, float& c)
{
    // recurrent dot: 4 partial accumulators per gate
    float s0 = aA,  s1 = 0.0f, s2 = 0.0f, s3 = 0.0f;
    float q0 = aB,  q1 = 0.0f, q2 = 0.0f, q3 = 0.0f;
#pragma unroll
    for (int k = 0; k < H; k += 4) {
        float h0 = __shfl_sync(FULL_MASK, h, k);
        float h1 = __shfl_sync(FULL_MASK, h, k + 1);
        float h2 = __shfl_sync(FULL_MASK, h, k + 2);
        float h3 = __shfl_sync(FULL_MASK, h, k + 3);
        s0 = fmaf(wA[k],     h0, s0);  q0 = fmaf(wB[k],     h0, q0);
        s1 = fmaf(wA[k + 1], h1, s1);  q1 = fmaf(wB[k + 1], h1, q1);
        s2 = fmaf(wA[k + 2], h2, s2);  q2 = fmaf(wB[k + 2], h2, q2);
        s3 = fmaf(wA[k + 3], h3, s3);  q3 = fmaf(wB[k + 3], h3, q3);
    }
    aA = (s0 + s1) + (s2 + s3);
    aB = (q0 + q1) + (q2 + q3);

    // gate A: sigmoid on both halves: sigma(x) = 0.5*tanh(0.5x) + 0.5
    float A  = fmaf(0.5f, tanh_fast(0.5f * aA), 0.5f);
    // gate B: tanh(g) on lower, sigmoid(o) on upper, branchless via constants
    float Bv = fmaf(cB, tanh_fast(mB * aB), dB);

    float P  = A * Bv;                          // lower: i*g
    float send1 = lower ? P : A;                // lower sends i*g, upper sends f
    float r1 = __shfl_xor_sync(FULL_MASK, send1, 16);
    float r2 = __shfl_xor_sync(FULL_MASK, Bv, 16); // issues early; o -> lower
    float F  = lower ? r1 : A;
    float Pu = lower ? P  : r1;
    c = fmaf(F, c, Pu);
    float tc = tanh_fast(c);
    float O  = lower ? r2 : Bv;
    h = O * tc;
}

// ---------------------------------------------------------------------------
__global__ void __launch_bounds__(96, 1) lstm_fused_kernel(
    const float* __restrict__ x, int B,
    const float* __restrict__ Wih0, const float* __restrict__ Whh0,
    const float* __restrict__ bih0, const float* __restrict__ bhh0,
    const float* __restrict__ Wih1, const float* __restrict__ Whh1,
    const float* __restrict__ bih1, const float* __restrict__ bhh1)
{
    extern __shared__ float smem[];
    float* xs  = smem;                       // [512]
    float* h1s = smem + T_STEPS;             // [512 * 16]
    float* xg1 = h1s + T_STEPS * H;          // [512 * 64]

    const int tid  = threadIdx.x;
    const int wid  = tid >> 5;
    const int lane = tid & 31;
    const bool lower = (lane < 16);
    const float mB = lower ? 1.0f : 0.5f;
    const float cB = lower ? 1.0f : 0.5f;
    const float dB = lower ? 0.0f : 0.5f;
    const int l = lane;

    // gather the single relevant batch row of x
    for (int t = tid; t < T_STEPS; t += 96)
        xs[t] = x[(size_t)t * B + (B - 1)];

    // per-role weights in registers
    float wA[H], wB[H];     // recurrence weights (warp 0: Whh0, warp 2: Whh1)
    float uA[H], uB[H];     // warp 1: Wih1 rows
    float bA = 0.0f, bB = 0.0f, wiA = 0.0f, wiB = 0.0f;

    if (wid == 0) {
#pragma unroll
        for (int k = 0; k < H; k++) {
            wA[k] = Whh0[l * H + k];
            wB[k] = Whh0[(l + 32) * H + k];
        }
        wiA = Wih0[l];       wiB = Wih0[l + 32];          // I = 1
        bA  = bih0[l] + bhh0[l];
        bB  = bih0[l + 32] + bhh0[l + 32];
    } else if (wid == 1) {
#pragma unroll
        for (int k = 0; k < H; k++) {
            uA[k] = Wih1[l * H + k];
            uB[k] = Wih1[(l + 32) * H + k];
        }
        bA = bih1[l] + bhh1[l];
        bB = bih1[l + 32] + bhh1[l + 32];
    } else if (wid == 2) {
#pragma unroll
        for (int k = 0; k < H; k++) {
            wA[k] = Whh1[l * H + k];
            wB[k] = Whh1[(l + 32) * H + k];
        }
    }
    __syncthreads();

    float h = 0.0f, c = 0.0f;

    for (int blk = 0; blk < NB + 2; blk++) {
        if (wid == 0) {
            if (blk < NB) {
                const int t0 = blk * BLK;
#pragma unroll 1
                for (int s = 0; s < BLK; s++) {
                    const int t = t0 + s;
                    const float xt = xs[t];
                    lstm_step(fmaf(wiA, xt, bA), fmaf(wiB, xt, bB),
                              wA, wB, lower, mB, cB, dB, h, c);
                    if (lower) h1s[t * H + lane] = h;
                }
            }
        } else if (wid == 1) {
            if (blk >= 1 && blk <= NB) {
                const int t0 = (blk - 1) * BLK;
#pragma unroll 1
                for (int s = 0; s < BLK; s++) {
                    const int t = t0 + s;
                    const float4* hp = reinterpret_cast<const float4*>(h1s + t * H);
                    float a = bA, b = bB;
#pragma unroll
                    for (int q = 0; q < 4; q++) {
                        float4 h4 = hp[q];                   // broadcast LDS.128
                        a = fmaf(uA[q * 4 + 0], h4.x, a);
                        b = fmaf(uB[q * 4 + 0], h4.x, b);
                        a = fmaf(uA[q * 4 + 1], h4.y, a);
                        b = fmaf(uB[q * 4 + 1], h4.y, b);
                        a = fmaf(uA[q * 4 + 2], h4.z, a);
                        b = fmaf(uB[q * 4 + 2], h4.z, b);
                        a = fmaf(uA[q * 4 + 3], h4.w, a);
                        b = fmaf(uB[q * 4 + 3], h4.w, b);
                    }
                    xg1[t * 64 + l]      = a;   // conflict-free (consecutive lanes)
                    xg1[t * 64 + l + 32] = b;
                }
            }
        } else if (wid == 2) {
            if (blk >= 2) {
                const int t0 = (blk - 2) * BLK;
#pragma unroll 1
                for (int s = 0; s < BLK; s++) {
                    const int t = t0 + s;
                    lstm_step(xg1[t * 64 + l], xg1[t * 64 + l + 32],
                              wA, wB, lower, mB, cB, dB, h, c);
                    if (lower) g_h2[t * H + lane] = h;
                }
            }
        }
        __syncthreads();   // uniform: all 96 threads, every round; drains STS
    }
}

// ---------------------------------------------------------------------------
// MLP head 16 -> 64 -> 32 -> 1 on the 512 rows of g_h2.
// Weights staged into shared; z2 restructured: unroll 4 + dual accumulators
// (8 independent FMA chains) to fix the 50% issue efficiency of the old
// 2-chain version.
// ---------------------------------------------------------------------------
__global__ void __launch_bounds__(32) mlp_kernel(
    const float* __restrict__ W1, const float* __restrict__ b1,
    const float* __restrict__ W2, const float* __restrict__ b2,
    const float* __restrict__ W3, const float* __restrict__ b3,
    float* __restrict__ out)
{
    __shared__ float sW1[64 * H];    // 1024
    __shared__ float sW2[32 * 64];   // 2048
    __shared__ float sb1[64];
    __shared__ float sb2[32];
    __shared__ float sW3[32];

    const int tid = threadIdx.x;

    // stage weights (vectorized, coalesced; all-lane broadcast reads later)
    for (int i = tid; i < (64 * H) / 4; i += 32)
        reinterpret_cast<float4*>(sW1)[i] = reinterpret_cast<const float4*>(W1)[i];
    for (int i = tid; i < (32 * 64) / 4; i += 32)
        reinterpret_cast<float4*>(sW2)[i] = reinterpret_cast<const float4*>(W2)[i];
    if (tid < 16) reinterpret_cast<float4*>(sb1)[tid] = reinterpret_cast<const float4*>(b1)[tid];
    if (tid < 8)  reinterpret_cast<float4*>(sb2)[tid] = reinterpret_cast<const float4*>(b2)[tid];
    if (tid < 8)  reinterpret_cast<float4*>(sW3)[tid] = reinterpret_cast<const float4*>(W3)[tid];
    __syncthreads();

    const int r = blockIdx.x * 32 + tid;   // 16 blocks * 32 = 512 rows
    const float bias3 = b3[0];

    float hv[H];
    const float4* hp = reinterpret_cast<const float4*>(g_h2 + r * H);
#pragma unroll
    for (int q = 0; q < H / 4; q++) {
        float4 v = hp[q];
        hv[q * 4 + 0] = v.x; hv[q * 4 + 1] = v.y;
        hv[q * 4 + 2] = v.z; hv[q * 4 + 3] = v.w;
    }

    float z1[64];
#pragma unroll 4
    for (int g = 0; g < 64; g++) {
        float a = sb1[g];
        const float4* w = reinterpret_cast<const float4*>(sW1 + g * H);
#pragma unroll
        for (int k4 = 0; k4 < H / 4; k4++) {
            float4 wv = w[k4];
            a = fmaf(wv.x, hv[k4 * 4 + 0], a);
            a = fmaf(wv.y, hv[k4 * 4 + 1], a);
            a = fmaf(wv.z, hv[k4 * 4 + 2], a);
            a = fmaf(wv.w, hv[k4 * 4 + 3], a);
        }
        z1[g] = fmaxf(a, 0.0f);
    }

    float z2[32];
#pragma unroll 4
    for (int g = 0; g < 32; g++) {
        float a0 = sb2[g], a1 = 0.0f;
        const float4* w = reinterpret_cast<const float4*>(sW2 + g * 64);
#pragma unroll
        for (int k4 = 0; k4 < 8; k4++) {
            float4 wv = w[k4];
            a0 = fmaf(wv.x, z1[k4 * 4 + 0], a0);
            a0 = fmaf(wv.y, z1[k4 * 4 + 1], a0);
            a0 = fmaf(wv.z, z1[k4 * 4 + 2], a0);
            a0 = fmaf(wv.w, z1[k4 * 4 + 3], a0);
        }
#pragma unroll
        for (int k4 = 8; k4 < 16; k4++) {
            float4 wv = w[k4];
            a1 = fmaf(wv.x, z1[k4 * 4 + 0], a1);
            a1 = fmaf(wv.y, z1[k4 * 4 + 1], a1);
            a1 = fmaf(wv.z, z1[k4 * 4 + 2], a1);
            a1 = fmaf(wv.w, z1[k4 * 4 + 3], a1);
        }
        z2[g] = fmaxf(a0 + a1, 0.0f);
    }

    float a0 = bias3, a1 = 0.0f;
#pragma unroll
    for (int k = 0; k < 16; k++) {
        a0 = fmaf(sW3[k],      z2[k],      a0);
        a1 = fmaf(sW3[k + 16], z2[k + 16], a1);
    }
    out[r] = a0 + a1;
}

// ---------------------------------------------------------------------------
extern "C" void kernel_launch(void* const* d_in, const int* in_sizes, int n_in,
                              void* d_out, int out_size)
{
    const float* x    = (const float*)d_in[0];
    const float* Wih0 = (const float*)d_in[1];
    const float* Whh0 = (const float*)d_in[2];
    const float* bih0 = (const float*)d_in[3];
    const float* bhh0 = (const float*)d_in[4];
    const float* Wih1 = (const float*)d_in[5];
    const float* Whh1 = (const float*)d_in[6];
    const float* bih1 = (const float*)d_in[7];
    const float* bhh1 = (const float*)d_in[8];
    const float* W1   = (const float*)d_in[9];
    const float* b1   = (const float*)d_in[10];
    const float* W2   = (const float*)d_in[11];
    const float* b2   = (const float*)d_in[12];
    const float* W3   = (const float*)d_in[13];
    const float* b3   = (const float*)d_in[14];

    const int B = in_sizes[0] / T_STEPS;   // 4096 (I = 1)

    // dynamic smem: xs(512) + h1s(512*16) + xg1(512*64) floats = 165,888 bytes
    const int smem_bytes = (T_STEPS + T_STEPS * H + T_STEPS * 64) * (int)sizeof(float);
    cudaFuncSetAttribute(lstm_fused_kernel,
                         cudaFuncAttributeMaxDynamicSharedMemorySize, smem_bytes);

    lstm_fused_kernel<<<1, 96, smem_bytes>>>(x, B,
        Wih0, Whh0, bih0, bhh0, Wih1, Whh1, bih1, bhh1);
    mlp_kernel<<<16, 32>>>(W1, b1, W2, b2, W3, b3, (float*)d_out);
}

// round 9
// speedup vs baseline: 4.1724x; 1.0758x over previous
#include <cuda_runtime.h>

// ---------------------------------------------------------------------------
// LSTM_Model: T=512, B=4096, I=1, H=16, two LSTM layers, then MLP 16->64->32->1
// Reference output = MLP(h2[:, B-1, :]) -> only batch row B-1 matters.
//
// Single fused kernel, 6 warps, SMSP = wid % 4:
//   wid 2 : layer-0 recurrence   (SMSP2, solo)
//   wid 3 : layer-1 recurrence   (SMSP3, solo)
//   wid 0 : layer-1 input-gate precompute xg1[t] = Wih1 @ h1[t] + b
//   wid 1,4,5 : MLP head, one warp per row, lag 3 blocks (hidden under LSTM)
// Handoff via 2-block shared rings; __syncthreads() per 16-step round.
// ---------------------------------------------------------------------------

#define T_STEPS 512
#define H 16
#define BLK 16
#define NB (T_STEPS / BLK)
#define RING 32                 // 2 blocks of 16 rows
#define FULL_MASK 0xffffffffu

__device__ __forceinline__ float tanh_fast(float x) {
    float y;
    asm("tanh.approx.f32 %0, %1;" : "=f"(y) : "f"(x));
    return y;
}

// One gate-split LSTM step (see R7/R8 notes).
__device__ __forceinline__ void lstm_step(
    float aA, float aB,
    const float* __restrict__ wA,
    const float* __restrict__ wB,
    bool lower, float mB, float cB, float dB,
    float& h, float& c)
{
    float s0 = aA,  s1 = 0.0f, s2 = 0.0f, s3 = 0.0f;
    float q0 = aB,  q1 = 0.0f, q2 = 0.0f, q3 = 0.0f;
#pragma unroll
    for (int k = 0; k < H; k += 4) {
        float h0 = __shfl_sync(FULL_MASK, h, k);
        float h1 = __shfl_sync(FULL_MASK, h, k + 1);
        float h2 = __shfl_sync(FULL_MASK, h, k + 2);
        float h3 = __shfl_sync(FULL_MASK, h, k + 3);
        s0 = fmaf(wA[k],     h0, s0);  q0 = fmaf(wB[k],     h0, q0);
        s1 = fmaf(wA[k + 1], h1, s1);  q1 = fmaf(wB[k + 1], h1, q1);
        s2 = fmaf(wA[k + 2], h2, s2);  q2 = fmaf(wB[k + 2], h2, q2);
        s3 = fmaf(wA[k + 3], h3, s3);  q3 = fmaf(wB[k + 3], h3, q3);
    }
    aA = (s0 + s1) + (s2 + s3);
    aB = (q0 + q1) + (q2 + q3);

    float A  = fmaf(0.5f, tanh_fast(0.5f * aA), 0.5f);      // sigmoid (i / f)
    float Bv = fmaf(cB, tanh_fast(mB * aB), dB);            // tanh g / sigmoid o

    float P  = A * Bv;                          // lower: i*g
    float send1 = lower ? P : A;                // lower sends i*g, upper sends f
    float r1 = __shfl_xor_sync(FULL_MASK, send1, 16);
    float r2 = __shfl_xor_sync(FULL_MASK, Bv, 16);
    float F  = lower ? r1 : A;
    float Pu = lower ? P  : r1;
    c = fmaf(F, c, Pu);
    float tc = tanh_fast(c);
    float O  = lower ? r2 : Bv;
    h = O * tc;
}

// ---------------------------------------------------------------------------
__global__ void __launch_bounds__(192, 1) lstm_fused_kernel(
    const float* __restrict__ x, int B,
    const float* __restrict__ Wih0, const float* __restrict__ Whh0,
    const float* __restrict__ bih0, const float* __restrict__ bhh0,
    const float* __restrict__ Wih1, const float* __restrict__ Whh1,
    const float* __restrict__ bih1, const float* __restrict__ bhh1,
    const float* __restrict__ W1, const float* __restrict__ b1,
    const float* __restrict__ W2, const float* __restrict__ b2,
    const float* __restrict__ W3, const float* __restrict__ b3,
    float* __restrict__ out)
{
    __shared__ float xs[T_STEPS];           // 2 KB
    __shared__ float h1r[RING * H];         // 2 KB ring: layer-0 h
    __shared__ float xg1r[RING * 64];       // 8 KB ring: layer-1 input gates
    __shared__ float h2r[RING * H];         // 2 KB ring: layer-1 h

    const int tid  = threadIdx.x;
    const int wid  = tid >> 5;
    const int lane = tid & 31;
    const bool lower = (lane < 16);
    const float mB = lower ? 1.0f : 0.5f;
    const float cB = lower ? 1.0f : 0.5f;
    const float dB = lower ? 0.0f : 0.5f;
    const int l = lane;

    // gather the single relevant batch row of x
    for (int t = tid; t < T_STEPS; t += 192)
        xs[t] = x[(size_t)t * B + (B - 1)];

    // ---------------- per-role setup ----------------
    // wid 2: L0 recurrence; wid 3: L1 recurrence; wid 0: precompute;
    // wid 1,4,5: MLP (index m = 0,1,2)
    const bool isL0  = (wid == 2);
    const bool isL1  = (wid == 3);
    const bool isPre = (wid == 0);
    const bool isMLP = (wid == 1 || wid >= 4);
    const int  m     = (wid == 1) ? 0 : (wid - 3);   // MLP warp index 0..2

    float wA[H], wB[H];                 // recurrence weights
    float uA[H], uB[H];                 // precompute: Wih1 rows
    float bA = 0.0f, bB = 0.0f, wiA = 0.0f, wiB = 0.0f;

    // MLP per-lane weights
    float w1a[H], w1b[H], w2v[64];
    float b1a = 0.0f, b1b = 0.0f, b2l = 0.0f, w3l = 0.0f, b3v = 0.0f;

    if (isL0) {
#pragma unroll
        for (int k = 0; k < H; k++) {
            wA[k] = Whh0[l * H + k];
            wB[k] = Whh0[(l + 32) * H + k];
        }
        wiA = Wih0[l];       wiB = Wih0[l + 32];          // I = 1
        bA  = bih0[l] + bhh0[l];
        bB  = bih0[l + 32] + bhh0[l + 32];
    } else if (isPre) {
#pragma unroll
        for (int k = 0; k < H; k++) {
            uA[k] = Wih1[l * H + k];
            uB[k] = Wih1[(l + 32) * H + k];
        }
        bA = bih1[l] + bhh1[l];
        bB = bih1[l + 32] + bhh1[l + 32];
    } else if (isL1) {
#pragma unroll
        for (int k = 0; k < H; k++) {
            wA[k] = Whh1[l * H + k];
            wB[k] = Whh1[(l + 32) * H + k];
        }
    } else {  // MLP warps
        const float4* w1p = reinterpret_cast<const float4*>(W1 + l * H);
        const float4* w1q = reinterpret_cast<const float4*>(W1 + (l + 32) * H);
#pragma unroll
        for (int q = 0; q < 4; q++) {
            float4 a = w1p[q], b = w1q[q];
            w1a[q*4+0]=a.x; w1a[q*4+1]=a.y; w1a[q*4+2]=a.z; w1a[q*4+3]=a.w;
            w1b[q*4+0]=b.x; w1b[q*4+1]=b.y; w1b[q*4+2]=b.z; w1b[q*4+3]=b.w;
        }
        const float4* w2p = reinterpret_cast<const float4*>(W2 + l * 64);
#pragma unroll
        for (int q = 0; q < 16; q++) {
            float4 v = w2p[q];
            w2v[q*4+0]=v.x; w2v[q*4+1]=v.y; w2v[q*4+2]=v.z; w2v[q*4+3]=v.w;
        }
        b1a = b1[l];  b1b = b1[l + 32];
        b2l = b2[l];  w3l = W3[l];  b3v = b3[0];
    }
    __syncthreads();

    float h = 0.0f, c = 0.0f;

    // rounds: L0 does block blk, Pre blk-1, L1 blk-2, MLP blk-3
    for (int blk = 0; blk < NB + 3; blk++) {
        if (isL0) {
            if (blk < NB) {
                const int t0 = blk * BLK;
#pragma unroll 1
                for (int s = 0; s < BLK; s++) {
                    const int t = t0 + s;
                    const float xt = xs[t];
                    lstm_step(fmaf(wiA, xt, bA), fmaf(wiB, xt, bB),
                              wA, wB, lower, mB, cB, dB, h, c);
                    if (lower) h1r[(t & (RING-1)) * H + lane] = h;
                }
            }
        } else if (isPre) {
            if (blk >= 1 && blk <= NB) {
                const int t0 = (blk - 1) * BLK;
#pragma unroll 1
                for (int s = 0; s < BLK; s++) {
                    const int t = t0 + s;
                    const float4* hp =
                        reinterpret_cast<const float4*>(h1r + (t & (RING-1)) * H);
                    float a = bA, b = bB;
#pragma unroll
                    for (int q = 0; q < 4; q++) {
                        float4 h4 = hp[q];
                        a = fmaf(uA[q*4+0], h4.x, a);  b = fmaf(uB[q*4+0], h4.x, b);
                        a = fmaf(uA[q*4+1], h4.y, a);  b = fmaf(uB[q*4+1], h4.y, b);
                        a = fmaf(uA[q*4+2], h4.z, a);  b = fmaf(uB[q*4+2], h4.z, b);
                        a = fmaf(uA[q*4+3], h4.w, a);  b = fmaf(uB[q*4+3], h4.w, b);
                    }
                    xg1r[(t & (RING-1)) * 64 + l]      = a;
                    xg1r[(t & (RING-1)) * 64 + l + 32] = b;
                }
            }
        } else if (isL1) {
            if (blk >= 2 && blk <= NB + 1) {
                const int t0 = (blk - 2) * BLK;
#pragma unroll 1
                for (int s = 0; s < BLK; s++) {
                    const int t = t0 + s;
                    lstm_step(xg1r[(t & (RING-1)) * 64 + l],
                              xg1r[(t & (RING-1)) * 64 + l + 32],
                              wA, wB, lower, mB, cB, dB, h, c);
                    if (lower) h2r[(t & (RING-1)) * H + lane] = h;
                }
            }
        } else {  // MLP warps: one warp per row, rows of block blk-3
            if (blk >= 3) {
                const int t0 = (blk - 3) * BLK;
#pragma unroll 1
                for (int s = m; s < BLK; s += 3) {
                    const int r = t0 + s;
                    const float4* hp =
                        reinterpret_cast<const float4*>(h2r + (r & (RING-1)) * H);
                    float hv[H];
#pragma unroll
                    for (int q = 0; q < 4; q++) {
                        float4 v = hp[q];
                        hv[q*4+0]=v.x; hv[q*4+1]=v.y; hv[q*4+2]=v.z; hv[q*4+3]=v.w;
                    }
                    // z1 gates l and l+32
                    float a = b1a, b = b1b;
#pragma unroll
                    for (int k = 0; k < H; k++) {
                        a = fmaf(w1a[k], hv[k], a);
                        b = fmaf(w1b[k], hv[k], b);
                    }
                    float z1a = fmaxf(a, 0.0f);
                    float z1b = fmaxf(b, 0.0f);
                    // z2 gate l: dot over all 64 z1 (broadcast via shuffle)
                    float acc0 = b2l, acc1 = 0.0f;
#pragma unroll
                    for (int k = 0; k < 32; k++) {
                        float za = __shfl_sync(FULL_MASK, z1a, k);
                        float zb = __shfl_sync(FULL_MASK, z1b, k);
                        acc0 = fmaf(w2v[k],      za, acc0);
                        acc1 = fmaf(w2v[k + 32], zb, acc1);
                    }
                    float z2v = fmaxf(acc0 + acc1, 0.0f);
                    // final dot: butterfly reduce of w3l * z2v
                    float p = w3l * z2v;
                    p += __shfl_xor_sync(FULL_MASK, p, 16);
                    p += __shfl_xor_sync(FULL_MASK, p, 8);
                    p += __shfl_xor_sync(FULL_MASK, p, 4);
                    p += __shfl_xor_sync(FULL_MASK, p, 2);
                    p += __shfl_xor_sync(FULL_MASK, p, 1);
                    if (lane == 0) out[r] = p + b3v;
                }
            }
        }
        __syncthreads();   // uniform: all 192 threads, every round; drains STS
    }
}

// ---------------------------------------------------------------------------
extern "C" void kernel_launch(void* const* d_in, const int* in_sizes, int n_in,
                              void* d_out, int out_size)
{
    const float* x    = (const float*)d_in[0];
    const float* Wih0 = (const float*)d_in[1];
    const float* Whh0 = (const float*)d_in[2];
    const float* bih0 = (const float*)d_in[3];
    const float* bhh0 = (const float*)d_in[4];
    const float* Wih1 = (const float*)d_in[5];
    const float* Whh1 = (const float*)d_in[6];
    const float* bih1 = (const float*)d_in[7];
    const float* bhh1 = (const float*)d_in[8];
    const float* W1   = (const float*)d_in[9];
    const float* b1   = (const float*)d_in[10];
    const float* W2   = (const float*)d_in[11];
    const float* b2   = (const float*)d_in[12];
    const float* W3   = (const float*)d_in[13];
    const float* b3   = (const float*)d_in[14];

    const int B = in_sizes[0] / T_STEPS;   // 4096 (I = 1)

    lstm_fused_kernel<<<1, 192>>>(x, B,
        Wih0, Whh0, bih0, bhh0, Wih1, Whh1, bih1, bhh1,
        W1, b1, W2, b2, W3, b3, (float*)d_out);
}